// round 1
// baseline (speedup 1.0000x reference)
#include <cuda_runtime.h>
#include <cstdint>

#define N_  64
#define C_  64
#define T_  128
#define V_  25
#define H_  3
#define DQ_ 32
#define O_  192   // 2*H*DQ

// ---------------- scratch (static __device__ — no allocations) ----------------
__device__ __align__(16) float g_pe[C_*V_];                 // 1600   pos embed (c,v)
__device__ __align__(16) float g_WqkvT[C_*O_];              // 12288  [c][o]
__device__ __align__(16) float g_Wt[960*64];                // 61440  conv W [k][co]
__device__ __align__(16) float g_attpart[N_*8*H_*V_*V_];    // 960000 gram partials
__device__ __align__(16) float g_att[N_*H_*V_*V_];          // 120000 final attention
__device__ __align__(16) float g_z[N_*C_*T_*V_];            // 13107200 conv output
__device__ __align__(16) float g_bnpart[1024*128];          // per-block BN partials
__device__ __align__(16) float g_bn[128];                   // per-channel scale/shift

// ---------------- f32x2 helpers (SASS FFMA2 path) ----------------
static __device__ __forceinline__ unsigned long long pack2(float a, float b){
  unsigned long long r;
  asm("mov.b64 %0, {%1, %2};" : "=l"(r) : "f"(a), "f"(b));
  return r;
}
static __device__ __forceinline__ void fma2(unsigned long long& d,
                                            unsigned long long a,
                                            unsigned long long b){
  asm("fma.rn.f32x2 %0, %1, %2, %0;" : "+l"(d) : "l"(a), "l"(b));
}
static __device__ __forceinline__ float lo2(unsigned long long v){ return __uint_as_float((unsigned)v); }
static __device__ __forceinline__ float hi2(unsigned long long v){ return __uint_as_float((unsigned)(v>>32)); }

// ---------------- init: pos-embed + weight transposes ----------------
__global__ void k_init(const float* __restrict__ Wqkv, const float* __restrict__ Wout) {
  const int stride = gridDim.x * blockDim.x;
  const int i0 = blockIdx.x * blockDim.x + threadIdx.x;
  // pe[c][v]: even c -> sin(v*div), odd c -> cos(v*div), div = 10000^(-(c/2)/32)
  for (int i = i0; i < C_*V_; i += stride) {
    int c = i / V_, v = i - (i / V_) * V_;
    int ii = c >> 1;
    float dv = __expf(-(2.0f * ii) * (logf(10000.0f) / 64.0f));
    float ang = (float)v * dv;
    g_pe[i] = (c & 1) ? cosf(ang) : sinf(ang);
  }
  // WqkvT[c*192+o] = Wqkv[o*64+c]
  for (int i = i0; i < C_*O_; i += stride) {
    int c = i / O_, o = i - (i / O_) * O_;
    g_WqkvT[i] = Wqkv[o * C_ + c];
  }
  // Wt[k*64+co] = Wout[co*960+k]
  for (int i = i0; i < 960*64; i += stride) {
    int k = i >> 6, co = i & 63;
    g_Wt[i] = Wout[co * 960 + k];
  }
}

// ---------------- kernel A: QK projection GEMM + Gram partials ----------------
// grid (8 t-chunks, 64 n), 192 threads. smem: W 48KB + xs 6.5KB + qk 19.5KB
__global__ __launch_bounds__(192) void k_qkatt(const float* __restrict__ x,
                                               const float* __restrict__ bqkv) {
  extern __shared__ float sm[];
  float* sW  = sm;                 // [c][o] 12288
  float* sxs = sW + 12288;         // [c][26] (col 25 = 0)
  float* sqk = sxs + 64*26;        // [o][26] (col 25 = 0)
  const int tid = threadIdx.x;
  const int n = blockIdx.y, tc = blockIdx.x;

  for (int i = tid; i < 12288; i += 192) sW[i] = g_WqkvT[i];
  if (tid < 64) sxs[tid*26 + 25] = 0.f;
  sqk[tid*26 + 25] = 0.f;

  float acc[10];
  #pragma unroll
  for (int s = 0; s < 10; ++s) acc[s] = 0.f;
  const int nslots = (tid < 147) ? 10 : 9;   // 1875 = 192*9 + 147
  const float bo = bqkv[tid];

  const int tbeg = tc * 16;
  for (int t = tbeg; t < tbeg + 16; ++t) {
    __syncthreads();
    for (int i = tid; i < 1600; i += 192) {
      int c = i / 25, v = i - c*25;
      sxs[c*26 + v] = x[(((size_t)n*C_ + c)*T_ + t)*V_ + v] + g_pe[i];
    }
    __syncthreads();
    { // GEMM: this thread computes qk[o=tid][u] for u=0..24 (13 u-pairs packed)
      unsigned long long a2[13];
      unsigned long long binit = pack2(bo, bo);
      #pragma unroll
      for (int j = 0; j < 13; ++j) a2[j] = binit;
      const float* wp = sW + tid;
      #pragma unroll 4
      for (int c = 0; c < 64; ++c) {
        float w = wp[c*192];
        unsigned long long w2 = pack2(w, w);
        const unsigned long long* xr = (const unsigned long long*)(sxs + c*26);
        #pragma unroll
        for (int j = 0; j < 13; ++j) fma2(a2[j], w2, xr[j]);
      }
      float* q = sqk + tid*26;
      #pragma unroll
      for (int j = 0; j < 12; ++j) { q[2*j] = lo2(a2[j]); q[2*j+1] = hi2(a2[j]); }
      q[24] = lo2(a2[12]);
    }
    __syncthreads();
    // Gram accumulate: S[h][u][v] += sum_c q[h*32+c][u]*k[96+h*32+c][v]
    #pragma unroll
    for (int s = 0; s < 10; ++s) {
      if (s >= nslots) break;
      int idx = tid + 192*s;
      int h = idx / 625; int r = idx - h*625;
      int u = r / 25, v = r - (r/25)*25;
      const float* qp = sqk + (h*32)*26 + u;
      const float* kp = sqk + (96 + h*32)*26 + v;
      float sum = 0.f;
      #pragma unroll
      for (int c = 0; c < 32; ++c) sum += qp[c*26] * kp[c*26];
      acc[s] += sum;
    }
  }
  float* op = g_attpart + ((size_t)n*8 + tc)*1875;
  for (int s = 0; s < nslots; ++s) op[tid + 192*s] = acc[s];
}

// ---------------- kernel A2: reduce partials + tanh*alpha + att0 ----------------
__global__ void k_att2(const float* __restrict__ alphas, const float* __restrict__ att0s) {
  int i = blockIdx.x * blockDim.x + threadIdx.x;
  if (i >= N_*1875) return;
  int n = i / 1875, r = i - n*1875;
  float s = 0.f;
  #pragma unroll
  for (int tc = 0; tc < 8; ++tc) s += g_attpart[((size_t)n*8 + tc)*1875 + r];
  int h = r / 625;
  g_att[i] = tanhf(s * (1.0f/4096.0f)) * alphas[h] + att0s[r];
}

// ---------------- kernel B: fused att-apply + 1x5 conv + BN partials ----------------
// grid (16 t-chunks, 64 n), 256 threads. smem: ypad 174KB + att 7.6KB + Wstage 5KB
__global__ __launch_bounds__(256, 1) void k_main(const float* __restrict__ x,
                                                 const float* __restrict__ bout) {
  extern __shared__ float sm[];
  float* ypad = sm;               // [ch=192][t=8][29], cols 0,1,27,28 zero
  float* satt = ypad + 192*8*29;  // [h][u][26] (col 25 = 0)
  float* sWc  = satt + 3*25*26;   // [kk=20][co=64] stage
  const int tid = threadIdx.x;
  const int tx = tid & 31, ty = tid >> 5;
  const int n = blockIdx.y;
  const int t0 = blockIdx.x * 8;

  for (int i = tid; i < 1875; i += 256) {
    int h = i / 625, r = i - h*625;
    int u = r / 25, v = r - (r/25)*25;
    satt[(h*25 + u)*26 + v] = g_att[(size_t)n*1875 + i];
  }
  for (int i = tid; i < 75; i += 256) satt[i*26 + 25] = 0.f;
  for (int i = tid; i < 192*8*4; i += 256) {
    int row = i >> 2, p = i & 3;
    int col = (p < 2) ? p : (p + 25);
    ypad[row*29 + col] = 0.f;
  }
  __syncthreads();

  // Phase 1: y[h*64+ci][t][v] = sum_u x[n,ci,t0+t,u] * att[h][u][v]
  #pragma unroll
  for (int rep = 0; rep < 2; ++rep) {
    int pidx = tid + 256*rep;
    int ci = pidx & 63, t = pidx >> 6;
    const float* xr = x + (((size_t)n*C_ + ci)*T_ + t0 + t)*V_;
    float xv[25];
    #pragma unroll
    for (int u = 0; u < 25; ++u) xv[u] = xr[u];
    #pragma unroll
    for (int h = 0; h < 3; ++h) {
      unsigned long long a2[13];
      #pragma unroll
      for (int j = 0; j < 13; ++j) a2[j] = 0ULL;
      #pragma unroll
      for (int u = 0; u < 25; ++u) {
        unsigned long long xp = pack2(xv[u], xv[u]);
        const unsigned long long* ar = (const unsigned long long*)(satt + (h*25 + u)*26);
        #pragma unroll
        for (int j = 0; j < 13; ++j) fma2(a2[j], xp, ar[j]);
      }
      float* yr = ypad + ((h*64 + ci)*8 + t)*29 + 2;
      #pragma unroll
      for (int j = 0; j < 12; ++j) { yr[2*j] = lo2(a2[j]); yr[2*j+1] = hi2(a2[j]); }
      yr[24] = lo2(a2[12]);
    }
  }

  // Phase 2: conv GEMM. Z[co][tv] = sum_{k=(ch*5+dv)} W[co][k] * ypad[ch][tv.t][tv.v+dv]
  int yoff[7];
  #pragma unroll
  for (int i = 0; i < 7; ++i) {
    int tv = tx + 32*i;
    yoff[i] = (tv/25)*29 + (tv - (tv/25)*25);
  }
  const int nv = (tx < 8) ? 7 : 6;   // 200 = 32*6 + 8

  unsigned long long acc0[7], acc1[7], acc2v[7], acc3[7];
  #pragma unroll
  for (int i = 0; i < 7; ++i) { acc0[i]=0ULL; acc1[i]=0ULL; acc2v[i]=0ULL; acc3[i]=0ULL; }

  for (int k0 = 0; k0 < 960; k0 += 20) {
    __syncthreads();
    for (int i = tid; i < 1280; i += 256) sWc[i] = g_Wt[k0*64 + i];
    __syncthreads();
    const int ch0 = k0 / 5;
    #pragma unroll
    for (int cc = 0; cc < 4; ++cc) {
      const float* yb = ypad + (ch0 + cc)*232;         // 8*29
      const float* wb = sWc + cc*320 + (ty << 3);      // [kk][co], kk = cc*5+dv
      #pragma unroll
      for (int dv = 0; dv < 5; ++dv) {
        unsigned long long w0 = *(const unsigned long long*)(wb + dv*64);
        unsigned long long w1 = *(const unsigned long long*)(wb + dv*64 + 2);
        unsigned long long w2 = *(const unsigned long long*)(wb + dv*64 + 4);
        unsigned long long w3 = *(const unsigned long long*)(wb + dv*64 + 6);
        #pragma unroll
        for (int i = 0; i < 7; ++i) {
          float yl = yb[yoff[i] + dv];
          unsigned long long yp = pack2(yl, yl);
          fma2(acc0[i],  w0, yp);
          fma2(acc1[i],  w1, yp);
          fma2(acc2v[i], w2, yp);
          fma2(acc3[i],  w3, yp);
        }
      }
    }
  }

  // Store z + per-channel BN partial sums
  float bsum[8], bsq[8];
  const size_t zbase = (((size_t)n*C_)*T_ + t0)*V_;

#define STORE_PAIR(ACC, J4) { \
    int co0 = (ty << 3) + 2*(J4); \
    float b0 = bout[co0], b1 = bout[co0+1]; \
    float s0=0.f,q0=0.f,s1=0.f,q1=0.f; \
    _Pragma("unroll") \
    for (int i = 0; i < 7; ++i) if (i < nv) { \
      int tv = tx + 32*i; \
      float z0 = lo2(ACC[i]) + b0; \
      float z1 = hi2(ACC[i]) + b1; \
      g_z[zbase + (size_t)co0*3200 + tv]      = z0; \
      g_z[zbase + (size_t)(co0+1)*3200 + tv]  = z1; \
      s0 += z0; q0 += z0*z0; s1 += z1; q1 += z1*z1; } \
    bsum[2*(J4)]   = s0; bsq[2*(J4)]   = q0; \
    bsum[2*(J4)+1] = s1; bsq[2*(J4)+1] = q1; }

  STORE_PAIR(acc0, 0)
  STORE_PAIR(acc1, 1)
  STORE_PAIR(acc2v, 2)
  STORE_PAIR(acc3, 3)
#undef STORE_PAIR

  #pragma unroll
  for (int off = 16; off > 0; off >>= 1) {
    #pragma unroll
    for (int j = 0; j < 8; ++j) {
      bsum[j] += __shfl_down_sync(0xffffffffu, bsum[j], off);
      bsq[j]  += __shfl_down_sync(0xffffffffu, bsq[j],  off);
    }
  }
  if (tx == 0) {
    float* bp = g_bnpart + ((size_t)blockIdx.y*16 + blockIdx.x)*128;
    #pragma unroll
    for (int j = 0; j < 8; ++j) {
      bp[(ty << 3) + j]      = bsum[j];
      bp[64 + (ty << 3) + j] = bsq[j];
    }
  }
}

// ---------------- kernel C: reduce BN partials -> scale/shift ----------------
__global__ void k_bnred(const float* __restrict__ gamma, const float* __restrict__ beta) {
  __shared__ float s[4][128];
  __shared__ float tot[128];
  const int tid = threadIdx.x;           // 512
  const int slot = tid & 127, part = tid >> 7;
  float sum = 0.f;
  for (int b = part; b < 1024; b += 4) sum += g_bnpart[(size_t)b*128 + slot];
  s[part][slot] = sum;
  __syncthreads();
  if (tid < 128) tot[tid] = s[0][tid] + s[1][tid] + s[2][tid] + s[3][tid];
  __syncthreads();
  if (tid < 64) {
    const float inv = 1.0f / 204800.0f;  // N*T*V
    float mean = tot[tid] * inv;
    float var  = tot[64 + tid] * inv - mean*mean;
    float a = gamma[tid] * rsqrtf(var + 1e-5f);
    g_bn[tid]      = a;
    g_bn[64 + tid] = beta[tid] - mean * a;
  }
}

// ---------------- kernel D: BN apply + residual + leaky relu ----------------
__global__ void k_out(const float* __restrict__ x, float* __restrict__ out) {
  const float4* z4 = (const float4*)g_z;
  const float4* x4 = (const float4*)x;
  float4* o4 = (float4*)out;
  const int total = (N_*C_*T_*V_) / 4;
  for (int i = blockIdx.x*blockDim.x + threadIdx.x; i < total; i += gridDim.x*blockDim.x) {
    int c = (i / 800) & 63;             // 800 float4 per (n,c) row block
    float a = g_bn[c], b = g_bn[64 + c];
    float4 z = z4[i], xx = x4[i], r;
    float v;
    v = z.x*a + b + xx.x; r.x = fmaxf(v, 0.1f*v);
    v = z.y*a + b + xx.y; r.y = fmaxf(v, 0.1f*v);
    v = z.z*a + b + xx.z; r.z = fmaxf(v, 0.1f*v);
    v = z.w*a + b + xx.w; r.w = fmaxf(v, 0.1f*v);
    o4[i] = r;
  }
}

// ---------------- launch ----------------
extern "C" void kernel_launch(void* const* d_in, const int* in_sizes, int n_in,
                              void* d_out, int out_size) {
  const float* x      = (const float*)d_in[0];
  const float* Wqkv   = (const float*)d_in[1];
  const float* bqkv   = (const float*)d_in[2];
  const float* alphas = (const float*)d_in[3];
  const float* att0s  = (const float*)d_in[4];
  const float* Wout   = (const float*)d_in[5];
  const float* bout   = (const float*)d_in[6];
  const float* gamma  = (const float*)d_in[7];
  const float* beta   = (const float*)d_in[8];
  float* out = (float*)d_out;

  cudaFuncSetAttribute(k_qkatt, cudaFuncAttributeMaxDynamicSharedMemorySize, 75776);
  cudaFuncSetAttribute(k_main,  cudaFuncAttributeMaxDynamicSharedMemorySize, 191096);

  k_init<<<64, 256>>>(Wqkv, Wout);
  k_qkatt<<<dim3(8, 64), 192, 75776>>>(x, bqkv);
  k_att2<<<(N_*1875 + 255)/256, 256>>>(alphas, att0s);
  k_main<<<dim3(16, 64), 256, 191096>>>(x, bout);
  k_bnred<<<1, 512>>>(gamma, beta);
  k_out<<<4096, 256>>>(x, out);
}

// round 2
// speedup vs baseline: 1.3024x; 1.3024x over previous
#include <cuda_runtime.h>
#include <cstdint>

#define N_  64
#define C_  64
#define T_  128
#define V_  25
#define H_  3
#define O_  192   // 2*H*DQ
#define CHS 233   // padded channel stride in k_main ypad (8*29 + 1)

// ---------------- scratch ----------------
__device__ __align__(16) float g_pe[C_*V_];
__device__ __align__(16) float g_WqkvT[C_*O_];              // [c][o]
__device__ __align__(16) float g_Wt[960*64];                // [k][co]
__device__ __align__(16) float g_attpart[64*8*300*26];      // gram partials (n,tc,row*4+cq,26)
__device__ __align__(16) float g_att[N_*H_*V_*V_];
__device__ __align__(16) float g_z[N_*C_*T_*V_];
__device__ __align__(16) float g_bnpart[2048*128];
__device__ __align__(16) float g_bn[128];

// ---------------- f32x2 helpers ----------------
static __device__ __forceinline__ unsigned long long pack2(float a, float b){
  unsigned long long r;
  asm("mov.b64 %0, {%1, %2};" : "=l"(r) : "f"(a), "f"(b));
  return r;
}
static __device__ __forceinline__ void fma2(unsigned long long& d,
                                            unsigned long long a,
                                            unsigned long long b){
  asm("fma.rn.f32x2 %0, %1, %2, %0;" : "+l"(d) : "l"(a), "l"(b));
}
static __device__ __forceinline__ float lo2(unsigned long long v){ return __uint_as_float((unsigned)v); }
static __device__ __forceinline__ float hi2(unsigned long long v){ return __uint_as_float((unsigned)(v>>32)); }

// ---------------- init ----------------
__global__ void k_init(const float* __restrict__ Wqkv, const float* __restrict__ Wout) {
  const int stride = gridDim.x * blockDim.x;
  const int i0 = blockIdx.x * blockDim.x + threadIdx.x;
  for (int i = i0; i < C_*V_; i += stride) {
    int c = i / V_, v = i - (i / V_) * V_;
    int ii = c >> 1;
    float dv = __expf(-(2.0f * ii) * (logf(10000.0f) / 64.0f));
    float ang = (float)v * dv;
    g_pe[i] = (c & 1) ? cosf(ang) : sinf(ang);
  }
  for (int i = i0; i < C_*O_; i += stride) {
    int c = i / O_, o = i - (i / O_) * O_;
    g_WqkvT[i] = Wqkv[o * C_ + c];
  }
  for (int i = i0; i < 960*64; i += stride) {
    int k = i >> 6, co = i & 63;
    g_Wt[i] = Wout[co * 960 + k];
  }
}

// ---------------- kernel A: QK GEMM + Gram (FMA2) ----------------
// grid (8 tc, 64 n), 384 threads, 2 CTAs/SM. smem 75776 B.
__global__ __launch_bounds__(384, 2) void k_qkatt(const float* __restrict__ x,
                                                  const float* __restrict__ bqkv) {
  extern __shared__ float sm[];
  float* sW  = sm;                 // [c][192]  12288
  float* sxs = sW + 12288;         // [c][26]   1664
  float* sqk = sxs + 1664;         // [o][26]   4992
  const int tid = threadIdx.x;
  const int n = blockIdx.y, tc = blockIdx.x;

  for (int i = tid; i < 12288; i += 384) sW[i] = g_WqkvT[i];
  if (tid < 64) sxs[tid*26 + 25] = 0.f;
  if (tid < 192) sqk[tid*26 + 25] = 0.f;

  // QK split: o = tid%192, part = tid/192 handles u-pair range
  const int o = tid % 192;
  const int part = tid / 192;
  const int j0 = part ? 7 : 0;
  const float bo = bqkv[o];

  // Gram: threads 0..299: row = tid>>2 (h*25+u), cq = tid&3 (c-quarter)
  const int grow = tid >> 2, gcq = tid & 3;
  const bool gact = (tid < 300);
  const int gh = grow / 25, gu = grow - (grow/25)*25;
  unsigned long long gacc[13];
  #pragma unroll
  for (int j = 0; j < 13; ++j) gacc[j] = 0ULL;

  const int tbeg = tc * 16;
  for (int t = tbeg; t < tbeg + 16; ++t) {
    __syncthreads();
    for (int i = tid; i < 1600; i += 384) {
      int c = i / 25, v = i - c*25;
      sxs[c*26 + v] = x[(((size_t)n*C_ + c)*T_ + t)*V_ + v] + g_pe[i];
    }
    __syncthreads();
    { // qk[o][u] for this part's u range
      unsigned long long a2[7];
      unsigned long long binit = pack2(bo, bo);
      #pragma unroll
      for (int jj = 0; jj < 7; ++jj) a2[jj] = binit;
      const float* wp = sW + o;
      #pragma unroll 4
      for (int c = 0; c < 64; ++c) {
        float w = wp[c*192];
        unsigned long long w2 = pack2(w, w);
        const unsigned long long* xr = (const unsigned long long*)(sxs + c*26) + j0;
        #pragma unroll
        for (int jj = 0; jj < 7; ++jj) fma2(a2[jj], w2, xr[jj]);
      }
      float* q = sqk + o*26;
      if (part == 0) {
        #pragma unroll
        for (int jj = 0; jj < 7; ++jj) { q[2*jj] = lo2(a2[jj]); q[2*jj+1] = hi2(a2[jj]); }
      } else {
        #pragma unroll
        for (int jj = 0; jj < 5; ++jj) { q[14+2*jj] = lo2(a2[jj]); q[15+2*jj] = hi2(a2[jj]); }
        q[24] = lo2(a2[5]);   // col 25 stays 0
      }
    }
    __syncthreads();
    if (gact) {
      #pragma unroll
      for (int c8 = 0; c8 < 8; ++c8) {
        int c = gcq*8 + c8;
        float qv = sqk[(gh*32 + c)*26 + gu];
        unsigned long long q2 = pack2(qv, qv);
        const unsigned long long* kp = (const unsigned long long*)(sqk + (96 + gh*32 + c)*26);
        #pragma unroll
        for (int j = 0; j < 13; ++j) fma2(gacc[j], q2, kp[j]);
      }
    }
  }
  if (gact) {
    unsigned long long* op = (unsigned long long*)(g_attpart + ((size_t)(n*8 + tc)*300 + tid)*26);
    #pragma unroll
    for (int j = 0; j < 13; ++j) op[j] = gacc[j];
  }
}

// ---------------- kernel A2: reduce + tanh ----------------
__global__ void k_att2(const float* __restrict__ alphas, const float* __restrict__ att0s) {
  int i = blockIdx.x * blockDim.x + threadIdx.x;
  if (i >= N_*1875) return;
  int n = i / 1875, r = i - n*1875;
  int h = r / 625, rr = r - h*625;
  int u = rr / 25, v = rr - (rr/25)*25;
  int row = h*25 + u;
  float s = 0.f;
  const float* base = g_attpart + ((size_t)(n*8)*300 + row*4)*26 + v;
  #pragma unroll
  for (int tc = 0; tc < 8; ++tc)
    #pragma unroll
    for (int cq = 0; cq < 4; ++cq)
      s += base[((size_t)tc*300 + cq)*26];
  g_att[i] = tanhf(s * (1.0f/4096.0f)) * alphas[h] + att0s[r];
}

// ---------------- kernel B: att-apply + conv + BN partials ----------------
// grid (16 tc, 64 n), 512 threads. smem = 192*233 + 1950 + 2560 floats = 196984 B
__global__ __launch_bounds__(512, 1) void k_main(const float* __restrict__ x,
                                                 const float* __restrict__ bout) {
  extern __shared__ float sm[];
  float* ypad = sm;                 // [ch=192][stride 233]: [t=8][29] + 1 pad
  float* satt = ypad + 192*CHS;     // [h*25+u][26]
  float* sWc  = satt + 1950;        // [kk=40][co=64]
  const int tid = threadIdx.x;
  const int tx = tid & 31;
  const int wid = tid >> 5;         // 0..15
  const int o8 = wid & 7;           // co octet
  const int half = wid >> 3;        // 0: slots 0..3, 1: slots 4..6
  const int n = blockIdx.y;
  const int t0 = blockIdx.x * 8;

  for (int i = tid; i < 1875; i += 512) {
    int h = i / 625, r = i - h*625;
    int u = r / 25, v = r - (r/25)*25;
    satt[(h*25 + u)*26 + v] = g_att[(size_t)n*1875 + i];
  }
  for (int i = tid; i < 75; i += 512) satt[i*26 + 25] = 0.f;
  for (int i = tid; i < 192*8*4; i += 512) {
    int row = i >> 2, p = i & 3;              // row = ch*8+t
    int ch = row >> 3, tt = row & 7;
    int col = (p < 2) ? p : (p + 25);
    ypad[ch*CHS + tt*29 + col] = 0.f;
  }
  __syncthreads();

  // Phase 1: y[h*64+ci][t][v] = sum_u x[n,ci,t0+t,u]*att[h][u][v]
  {
    int ci = tid & 63, t = tid >> 6;          // 512 = 64*8
    const float* xr = x + (((size_t)n*C_ + ci)*T_ + t0 + t)*V_;
    float xv[25];
    #pragma unroll
    for (int u = 0; u < 25; ++u) xv[u] = xr[u];
    #pragma unroll
    for (int h = 0; h < 3; ++h) {
      unsigned long long a2[13];
      #pragma unroll
      for (int j = 0; j < 13; ++j) a2[j] = 0ULL;
      #pragma unroll
      for (int u = 0; u < 25; ++u) {
        unsigned long long xp = pack2(xv[u], xv[u]);
        const unsigned long long* ar = (const unsigned long long*)(satt + (h*25 + u)*26);
        #pragma unroll
        for (int j = 0; j < 13; ++j) fma2(a2[j], xp, ar[j]);
      }
      float* yr = ypad + (h*64 + ci)*CHS + t*29 + 2;
      #pragma unroll
      for (int j = 0; j < 12; ++j) { yr[2*j] = lo2(a2[j]); yr[2*j+1] = hi2(a2[j]); }
      yr[24] = lo2(a2[12]);
    }
  }

  // Phase 2 setup: slots
  int yoff[4];
  bool valid[4];
  const int nsi = half ? 3 : 4;
  #pragma unroll
  for (int si = 0; si < 4; ++si) {
    int s = half ? (4 + si) : si;
    int tv = tx + 32*s;
    valid[si] = (si < nsi) && (tv < 200);
    int tvc = tv < 200 ? tv : 199;
    yoff[si] = (tvc/25)*29 + (tvc - (tvc/25)*25);
  }

  unsigned long long acc[4][4];
  #pragma unroll
  for (int j = 0; j < 4; ++j)
    #pragma unroll
    for (int si = 0; si < 4; ++si) acc[j][si] = 0ULL;

  for (int k0 = 0; k0 < 960; k0 += 40) {
    __syncthreads();
    for (int i = tid; i < 2560; i += 512) sWc[i] = g_Wt[k0*64 + i];
    __syncthreads();
    const int ch0 = k0 / 5;
    #pragma unroll
    for (int cc = 0; cc < 8; ++cc) {
      const float* yb = ypad + (ch0 + cc)*CHS;
      const float* wb = sWc + cc*320 + (o8 << 3);
      #pragma unroll
      for (int dv = 0; dv < 5; ++dv) {
        unsigned long long w0 = *(const unsigned long long*)(wb + dv*64);
        unsigned long long w1 = *(const unsigned long long*)(wb + dv*64 + 2);
        unsigned long long w2 = *(const unsigned long long*)(wb + dv*64 + 4);
        unsigned long long w3 = *(const unsigned long long*)(wb + dv*64 + 6);
        if (half == 0) {
          #pragma unroll
          for (int si = 0; si < 4; ++si) {
            float yl = yb[yoff[si] + dv];
            unsigned long long yp = pack2(yl, yl);
            fma2(acc[0][si], w0, yp);
            fma2(acc[1][si], w1, yp);
            fma2(acc[2][si], w2, yp);
            fma2(acc[3][si], w3, yp);
          }
        } else {
          #pragma unroll
          for (int si = 0; si < 3; ++si) {
            float yl = yb[yoff[si] + dv];
            unsigned long long yp = pack2(yl, yl);
            fma2(acc[0][si], w0, yp);
            fma2(acc[1][si], w1, yp);
            fma2(acc[2][si], w2, yp);
            fma2(acc[3][si], w3, yp);
          }
        }
      }
    }
  }

  // Store z + BN partials
  float bsum[8], bsq[8];
  const size_t zbase = (size_t)n*204800 + (size_t)t0*25;

  #pragma unroll
  for (int j = 0; j < 4; ++j) {
    int co0 = (o8 << 3) + 2*j;
    float b0 = bout[co0], b1 = bout[co0+1];
    float s0=0.f,q0=0.f,s1=0.f,q1=0.f;
    #pragma unroll
    for (int si = 0; si < 4; ++si) {
      if (valid[si]) {
        int s = half ? (4 + si) : si;
        int tv = tx + 32*s;
        float z0 = lo2(acc[j][si]) + b0;
        float z1 = hi2(acc[j][si]) + b1;
        g_z[zbase + (size_t)co0*3200 + tv]     = z0;
        g_z[zbase + (size_t)(co0+1)*3200 + tv] = z1;
        s0 += z0; q0 += z0*z0; s1 += z1; q1 += z1*z1;
      }
    }
    bsum[2*j] = s0; bsq[2*j] = q0; bsum[2*j+1] = s1; bsq[2*j+1] = q1;
  }

  #pragma unroll
  for (int off = 16; off > 0; off >>= 1) {
    #pragma unroll
    for (int j = 0; j < 8; ++j) {
      bsum[j] += __shfl_down_sync(0xffffffffu, bsum[j], off);
      bsq[j]  += __shfl_down_sync(0xffffffffu, bsq[j],  off);
    }
  }
  if (tx == 0) {
    float* bp = g_bnpart + (((size_t)blockIdx.y*16 + blockIdx.x)*2 + half)*128;
    #pragma unroll
    for (int j = 0; j < 8; ++j) {
      bp[(o8 << 3) + j]      = bsum[j];
      bp[64 + (o8 << 3) + j] = bsq[j];
    }
  }
}

// ---------------- kernel C: BN reduce ----------------
__global__ void k_bnred(const float* __restrict__ gamma, const float* __restrict__ beta) {
  __shared__ float s[4][128];
  __shared__ float tot[128];
  const int tid = threadIdx.x;           // 512
  const int slot = tid & 127, part = tid >> 7;
  float sum = 0.f;
  for (int b = part; b < 2048; b += 4) sum += g_bnpart[(size_t)b*128 + slot];
  s[part][slot] = sum;
  __syncthreads();
  if (tid < 128) tot[tid] = s[0][tid] + s[1][tid] + s[2][tid] + s[3][tid];
  __syncthreads();
  if (tid < 64) {
    const float inv = 1.0f / 204800.0f;
    float mean = tot[tid] * inv;
    float var  = tot[64 + tid] * inv - mean*mean;
    float a = gamma[tid] * rsqrtf(var + 1e-5f);
    g_bn[tid]      = a;
    g_bn[64 + tid] = beta[tid] - mean * a;
  }
}

// ---------------- kernel D: epilogue ----------------
__global__ void k_out(const float* __restrict__ x, float* __restrict__ out) {
  const float4* z4 = (const float4*)g_z;
  const float4* x4 = (const float4*)x;
  float4* o4 = (float4*)out;
  const int total = (N_*C_*T_*V_) / 4;
  for (int i = blockIdx.x*blockDim.x + threadIdx.x; i < total; i += gridDim.x*blockDim.x) {
    int c = (i / 800) & 63;
    float a = g_bn[c], b = g_bn[64 + c];
    float4 z = z4[i], xx = x4[i], r;
    float v;
    v = z.x*a + b + xx.x; r.x = fmaxf(v, 0.1f*v);
    v = z.y*a + b + xx.y; r.y = fmaxf(v, 0.1f*v);
    v = z.z*a + b + xx.z; r.z = fmaxf(v, 0.1f*v);
    v = z.w*a + b + xx.w; r.w = fmaxf(v, 0.1f*v);
    o4[i] = r;
  }
}

// ---------------- launch ----------------
extern "C" void kernel_launch(void* const* d_in, const int* in_sizes, int n_in,
                              void* d_out, int out_size) {
  const float* x      = (const float*)d_in[0];
  const float* Wqkv   = (const float*)d_in[1];
  const float* bqkv   = (const float*)d_in[2];
  const float* alphas = (const float*)d_in[3];
  const float* att0s  = (const float*)d_in[4];
  const float* Wout   = (const float*)d_in[5];
  const float* bout   = (const float*)d_in[6];
  const float* gamma  = (const float*)d_in[7];
  const float* beta   = (const float*)d_in[8];
  float* out = (float*)d_out;

  cudaFuncSetAttribute(k_qkatt, cudaFuncAttributeMaxDynamicSharedMemorySize, 75776);
  cudaFuncSetAttribute(k_main,  cudaFuncAttributeMaxDynamicSharedMemorySize, 196984);

  k_init<<<64, 256>>>(Wqkv, Wout);
  k_qkatt<<<dim3(8, 64), 384, 75776>>>(x, bqkv);
  k_att2<<<(N_*1875 + 255)/256, 256>>>(alphas, att0s);
  k_main<<<dim3(16, 64), 512, 196984>>>(x, bout);
  k_bnred<<<1, 512>>>(gamma, beta);
  k_out<<<4096, 256>>>(x, out);
}